// round 1
// baseline (speedup 1.0000x reference)
#include <cuda_runtime.h>

// IF spiking neuron, T=4.
// x: [T*B, C, H, W] fp32 viewed as [T, B*C*H*W]; per position:
//   mem = 0.5*th; for t: mem += x[t]; s = (mem>=th)?th:0; out[t]=s; mem -= s;
// Pure streaming: 128 MiB in + 128 MiB out. One thread = one float4 lane
// across all 4 timesteps; loads batched first for MLP=4.

#define TSTEPS 4

__global__ __launch_bounds__(256, 8)
void if_kernel(const float4* __restrict__ x,
               const float*  __restrict__ thresh,
               float4* __restrict__ out,
               int n4, int stride4)
{
    int i = blockIdx.x * blockDim.x + threadIdx.x;
    if (i >= n4) return;

    const float th = __ldg(thresh);

    // Batch all 4 strided loads up-front (independent -> MLP=4 per thread).
    float4 xt[TSTEPS];
#pragma unroll
    for (int t = 0; t < TSTEPS; t++)
        xt[t] = x[i + t * stride4];

    float4 sp[TSTEPS];
    float* xf = reinterpret_cast<float*>(xt);
    float* sf = reinterpret_cast<float*>(sp);

    // Per-component sequential membrane recurrence (4 independent chains).
#pragma unroll
    for (int c = 0; c < 4; c++) {
        float m = 0.5f * th;
#pragma unroll
        for (int t = 0; t < TSTEPS; t++) {
            m += xf[t * 4 + c];
            float s = (m >= th) ? th : 0.0f;
            sf[t * 4 + c] = s;
            m -= s;
        }
    }

#pragma unroll
    for (int t = 0; t < TSTEPS; t++)
        out[i + t * stride4] = sp[t];
}

extern "C" void kernel_launch(void* const* d_in, const int* in_sizes, int n_in,
                              void* d_out, int out_size)
{
    const float* x      = (const float*)d_in[0];
    const float* thresh = (const float*)d_in[1];
    float* out          = (float*)d_out;

    int n = in_sizes[0];              // total elements (T * B*C*H*W)
    int stride = n / TSTEPS;          // elements per timestep slab
    int stride4 = stride / 4;         // float4 units per slab
    int n4 = stride4;                 // float4 lanes handled (one per thread)

    int threads = 256;
    int blocks = (n4 + threads - 1) / threads;
    if_kernel<<<blocks, threads>>>(
        (const float4*)x, thresh, (float4*)out, n4, stride4);
}